// round 3
// baseline (speedup 1.0000x reference)
#include <cuda_runtime.h>
#include <cuda_bf16.h>

// Problem constants (fixed shapes from reference)
#define M_DIM 4096
#define K_DIM 4096
#define B_DIM 4
#define N_DIM 2048
#define NNZR  409
#define NNZ_TOT (M_DIM * NNZR)

// Tiling
#define KB      128                 // K per stage (smem tile rows)
#define NSTAGE  (K_DIM / KB)        // 32
#define TN      128                 // n-columns per block
#define RB      128                 // rows per block
#define TPAD    132                 // padded tile row stride (floats), keeps 16B align

// Scratch (static __device__ — no runtime allocation)
__device__ float g_xT[(size_t)B_DIM * K_DIM * N_DIM];          // x transposed: [B][K][N]
__device__ int   g_bound[(NSTAGE + 1) * M_DIM];                // CSR segment boundaries per (stage, row)

// ---------------------------------------------------------------------------
// Kernel 1: transpose x [B,N,K] -> xT [B,K,N] (coalesced 32x32 tiles)
// ---------------------------------------------------------------------------
__global__ void transpose_kernel(const float* __restrict__ x) {
    __shared__ float tile[32][33];
    const int b  = blockIdx.z;
    const int k0 = blockIdx.x * 32;
    const int n0 = blockIdx.y * 32;
    const float* xb = x    + (size_t)b * N_DIM * K_DIM;
    float*       xt = g_xT + (size_t)b * K_DIM * N_DIM;

#pragma unroll
    for (int i = 0; i < 32; i += 8)
        tile[threadIdx.y + i][threadIdx.x] =
            xb[(size_t)(n0 + threadIdx.y + i) * K_DIM + (k0 + threadIdx.x)];
    __syncthreads();
#pragma unroll
    for (int i = 0; i < 32; i += 8)
        xt[(size_t)(k0 + threadIdx.y + i) * N_DIM + (n0 + threadIdx.x)] =
            tile[threadIdx.x][threadIdx.y + i];
}

// ---------------------------------------------------------------------------
// Kernel 2: per-(stage, row) CSR segment boundary via binary search.
// Columns are sorted within each row, so nnz with col in [s*KB,(s+1)*KB)
// form a contiguous range [bound[s][m], bound[s+1][m]).
// Layout stage-major: g_bound[s * M + m] for coalesced warp loads in SpMM.
// ---------------------------------------------------------------------------
__global__ void bound_kernel(const int* __restrict__ row_offsets,
                             const int* __restrict__ cols) {
    int idx = blockIdx.x * blockDim.x + threadIdx.x;
    if (idx >= (NSTAGE + 1) * M_DIM) return;
    int s = idx / M_DIM;
    int m = idx % M_DIM;
    int lo = row_offsets[m];
    int hi = row_offsets[m + 1];
    int target = s * KB;
    while (lo < hi) {
        int mid = (lo + hi) >> 1;
        if (cols[mid] < target) lo = mid + 1; else hi = mid;
    }
    g_bound[idx] = lo;
}

// ---------------------------------------------------------------------------
// Kernel 3: SpMM. Block = (n-tile of 128, row-block of 128, batch).
// K looped in 32 stages of 128; per stage the xT tile [128 x 128] is staged
// in SMEM (padded to 132 floats/row). 8 warps x 16 rows each; lane owns 4 n.
// (v,col) are fetched 32-at-a-time with coalesced loads and distributed via
// __shfl_sync, so the inner loop has no global-latency dependency chain:
// per nnz = 2 SHFL + 1 LDS.128 + 4 FFMA feeding 128 FMA-lanes.
// ---------------------------------------------------------------------------
extern __shared__ float xtile[];   // KB * TPAD floats = 67584 B

__global__ __launch_bounds__(256, 2)
void spmm_kernel(const float* __restrict__ vals,
                 const int*   __restrict__ cols,
                 float*       __restrict__ out) {
    const int tid  = threadIdx.x;
    const int lane = tid & 31;
    const int wid  = tid >> 5;
    const int b    = blockIdx.z;
    const int n0   = blockIdx.x * TN;
    const int mw   = blockIdx.y * RB + wid * 16;   // first row of this warp

    const float* xt = g_xT + (size_t)b * K_DIM * N_DIM;

    float4 acc[16];
#pragma unroll
    for (int r = 0; r < 16; ++r) acc[r] = make_float4(0.f, 0.f, 0.f, 0.f);

    for (int s = 0; s < NSTAGE; ++s) {
        // --- stage xT[b][s*KB .. s*KB+127][n0 .. n0+127] into SMEM ---
#pragma unroll
        for (int i = 0; i < 16; ++i) {
            int p = i * 256 + tid;           // 4096 float4s total
            int c = p >> 5;                  // tile row 0..127
            int q = p & 31;                  // float4 within row
            float4 v4 = *reinterpret_cast<const float4*>(
                xt + (size_t)(s * KB + c) * N_DIM + n0 + q * 4);
            *reinterpret_cast<float4*>(xtile + c * TPAD + q * 4) = v4;
        }
        __syncthreads();

        // --- load this warp's 16 row boundaries (coalesced, stage-major) ---
        // lanes 0..15: lo of rows r=lane      (bound[s][m])
        // lanes 16..31: hi of rows r=lane-16  (bound[s+1][m])
        int li  = lane & 15;
        int bnd = g_bound[(s + (lane >> 4)) * M_DIM + mw + li];

#pragma unroll
        for (int r = 0; r < 16; ++r) {
            int lo = __shfl_sync(0xffffffffu, bnd, r);
            int hi = __shfl_sync(0xffffffffu, bnd, r + 16);
            for (int base = lo; base < hi; base += 32) {
                int cnt = hi - base; if (cnt > 32) cnt = 32;
                int idx = base + lane; if (idx >= hi) idx = hi - 1;  // clamp (base<hi)
                float vr = vals[idx];
                int   cr = cols[idx] - s * KB;
                for (int j = 0; j < cnt; ++j) {
                    float v = __shfl_sync(0xffffffffu, vr, j);
                    int   c = __shfl_sync(0xffffffffu, cr, j);
                    const float4 xv = *reinterpret_cast<const float4*>(
                        xtile + c * TPAD + lane * 4);
                    acc[r].x = fmaf(v, xv.x, acc[r].x);
                    acc[r].y = fmaf(v, xv.y, acc[r].y);
                    acc[r].z = fmaf(v, xv.z, acc[r].z);
                    acc[r].w = fmaf(v, xv.w, acc[r].w);
                }
            }
        }
        __syncthreads();
    }

    // --- epilogue: out[b][m][n0 + 4*lane .. +3], coalesced float4 stores ---
    float* ob = out + ((size_t)b * M_DIM + mw) * N_DIM + n0;
#pragma unroll
    for (int r = 0; r < 16; ++r)
        *reinterpret_cast<float4*>(ob + (size_t)r * N_DIM + lane * 4) = acc[r];
}

// ---------------------------------------------------------------------------
// Launch: inputs per metadata order: x, values, row_offsets, column_indices
// ---------------------------------------------------------------------------
extern "C" void kernel_launch(void* const* d_in, const int* in_sizes, int n_in,
                              void* d_out, int out_size) {
    const float* x    = (const float*)d_in[0];
    const float* vals = (const float*)d_in[1];
    const int*   ro   = (const int*)d_in[2];
    const int*   cols = (const int*)d_in[3];
    float*       out  = (float*)d_out;

    (void)in_sizes; (void)n_in; (void)out_size;

    // >48KB dynamic smem opt-in (idempotent, host-side, capture-safe)
    cudaFuncSetAttribute(spmm_kernel, cudaFuncAttributeMaxDynamicSharedMemorySize,
                         KB * TPAD * (int)sizeof(float));

    dim3 tb(32, 8);
    dim3 tg(K_DIM / 32, N_DIM / 32, B_DIM);
    transpose_kernel<<<tg, tb>>>(x);

    int total = (NSTAGE + 1) * M_DIM;
    bound_kernel<<<(total + 255) / 256, 256>>>(ro, cols);

    dim3 sg(N_DIM / TN, M_DIM / RB, B_DIM);
    spmm_kernel<<<sg, 256, KB * TPAD * (int)sizeof(float)>>>(vals, cols, out);
}

// round 8
// speedup vs baseline: 1.8167x; 1.8167x over previous
#include <cuda_runtime.h>
#include <cuda_fp16.h>
#include <cstdint>

// ---------------- problem constants ----------------
#define M_DIM 4096
#define K_DIM 4096
#define B_DIM 4
#define N_DIM 2048
#define NNZR  409
#define NNZ_TOT (M_DIM * NNZR)

// ---------------- GEMM tiling ----------------
#define KB      64            // K per stage (64 fp16 = 128 B/row = one SW128 atom row)
#define KSTAGES (K_DIM / KB)  // 64
#define TM      128           // M rows per CTA
#define TN      128           // n columns per CTA

// ---------------- static scratch (no runtime allocation) ----------------
__device__ __half   g_xh[(size_t)B_DIM * N_DIM * K_DIM];     // x in fp16, [B][N][K]
__device__ uint32_t g_wpack[NNZ_TOT];                        // (fp16 val << 16) | col
__device__ int      g_bound[(KSTAGES + 1) * M_DIM];          // packed-index bounds per (stage,row)

// ---------------- SMEM ----------------
// xbuf0 | xbuf1 | wbuf0 | wbuf1, each 128 rows x 128 B (SW128-swizzled)
#define TILE_BYTES 16384
#define SM_TOTAL   (4 * TILE_BYTES)   // 64 KB dynamic

__device__ __forceinline__ uint32_t smem_u32(const void* p) {
    return (uint32_t)__cvta_generic_to_shared(p);
}
__device__ __forceinline__ void cp_async16(uint32_t dst, const void* src) {
    asm volatile("cp.async.cg.shared.global [%0], [%1], 16;" :: "r"(dst), "l"(src));
}
__device__ __forceinline__ void cp_commit() {
    asm volatile("cp.async.commit_group;");
}
__device__ __forceinline__ void cp_wait1() {
    asm volatile("cp.async.wait_group 1;" ::: "memory");
}
__device__ __forceinline__ void ldsm_x4(uint32_t* r, uint32_t addr) {
    asm volatile("ldmatrix.sync.aligned.m8n8.x4.shared.b16 {%0,%1,%2,%3}, [%4];"
                 : "=r"(r[0]), "=r"(r[1]), "=r"(r[2]), "=r"(r[3]) : "r"(addr));
}
__device__ __forceinline__ void mma16816(float* d, const uint32_t* a,
                                         uint32_t b0, uint32_t b1) {
    asm volatile(
        "mma.sync.aligned.m16n8k16.row.col.f32.f16.f16.f32 "
        "{%0,%1,%2,%3}, {%4,%5,%6,%7}, {%8,%9}, {%0,%1,%2,%3};"
        : "+f"(d[0]), "+f"(d[1]), "+f"(d[2]), "+f"(d[3])
        : "r"(a[0]), "r"(a[1]), "r"(a[2]), "r"(a[3]), "r"(b0), "r"(b1));
}

// ---------------------------------------------------------------------------
// Kernel 1: x fp32 -> fp16, same [B][N][K] layout (K-major rows = col-major
// KxN = exactly mma.sync's B operand layout; no transpose needed).
// ---------------------------------------------------------------------------
__global__ void convert_kernel(const float* __restrict__ x) {
    size_t i = ((size_t)blockIdx.x * blockDim.x + threadIdx.x) * 4;
    float4 v = *reinterpret_cast<const float4*>(x + i);
    __half2 h0 = __floats2half2_rn(v.x, v.y);
    __half2 h1 = __floats2half2_rn(v.z, v.w);
    uint2 pk = make_uint2(*(uint32_t*)&h0, *(uint32_t*)&h1);
    *reinterpret_cast<uint2*>(g_xh + i) = pk;
}

// ---------------------------------------------------------------------------
// Kernel 2: prep. Thread per row: merge adjacent duplicate columns (sorted),
// pack (fp16(sum) << 16 | col), record per-64-wide-stage bounds.
// ---------------------------------------------------------------------------
__global__ void prep_kernel(const float* __restrict__ vals,
                            const int*   __restrict__ cols) {
    int m = blockIdx.x * blockDim.x + threadIdx.x;
    if (m >= M_DIM) return;
    int rs = m * NNZR, re = rs + NNZR;
    int w = rs;
    int cur_stage = 0;
    g_bound[m] = rs;
    int pc = -1;
    float sum = 0.f;
    for (int i = rs; i < re; ++i) {
        int   c = cols[i];
        float v = vals[i];
        if (c == pc) { sum += v; continue; }
        if (pc >= 0) {
            __half h = __float2half_rn(sum);
            g_wpack[w++] = ((uint32_t)__half_as_ushort(h) << 16) | (uint32_t)pc;
        }
        int st = c / KB;
        for (int t = cur_stage + 1; t <= st; ++t) g_bound[t * M_DIM + m] = w;
        cur_stage = st;
        pc = c; sum = v;
    }
    __half h = __float2half_rn(sum);
    g_wpack[w++] = ((uint32_t)__half_as_ushort(h) << 16) | (uint32_t)pc;
    for (int t = cur_stage + 1; t <= KSTAGES; ++t) g_bound[t * M_DIM + m] = w;
}

// ---------------------------------------------------------------------------
// Kernel 3: HMMA SpMM-as-GEMM. CTA = 128M x 128N (one b). K in 64 stages of
// 64, double-buffered. Role split per stage: threads 0-127 zero+scatter their
// own W row (no intra-tile dependency); threads 128-255 cp.async next X tile.
// 8 warps (2m x 4n), each 64x32 via 16x m16n8k16 per k16-step.
// Swizzle: SW128 -> off ^ ((row&7)<<4), folded into an add (low7(row*128)=0).
// ---------------------------------------------------------------------------
extern __shared__ char smem[];

__global__ __launch_bounds__(256, 2)
void spmm_hmma_kernel(float* __restrict__ out) {
    const int tid  = threadIdx.x;
    const int lane = tid & 31;
    const int wid  = tid >> 5;

    const int nch = blockIdx.x;            // 0..63
    const int mb  = blockIdx.y;            // 0..31
    const int b   = nch >> 4;
    const int n0  = (nch & 15) * TN;
    const int m0  = mb * TM;

    const uint32_t sb = smem_u32(smem);

    const __half* xrow0 = g_xh + (size_t)(b * N_DIM + n0) * K_DIM;

    // warp tile origin: 2 m-warps x 4 n-warps
    const int wm = (wid & 1) * 64;
    const int wn = (wid >> 1) * 32;

    // ldmatrix lane address components
    const int arow = wm + (lane & 15);     // A row within tile (mt adds +16k)
    const int brow = wn + (lane & 15);     // B row within tile (np adds +16)
    const int seg16 = (lane >> 4) * 16;    // k-half byte offset

    float acc[4][4][4];
#pragma unroll
    for (int mt = 0; mt < 4; ++mt)
#pragma unroll
        for (int nt = 0; nt < 4; ++nt)
#pragma unroll
            for (int r = 0; r < 4; ++r) acc[mt][nt][r] = 0.f;

    // ---- prologue: issue X[0] (threads 128-255), everyone commits ----
    if (tid >= 128) {
        const char* src0 = (const char*)xrow0;
        int t = tid - 128;
#pragma unroll
        for (int i = 0; i < 8; ++i) {
            int p = i * 128 + t;           // 1024 chunks of 16 B
            int n = p >> 3, q = p & 7;
            cp_async16(sb + n * 128 + ((q * 16) ^ ((n & 7) << 4)),
                       src0 + (size_t)n * (K_DIM * 2) + q * 16);
        }
    }
    cp_commit();

    for (int s = 0; s < KSTAGES; ++s) {
        const int buf = s & 1;
        const uint32_t xbase = sb + buf * TILE_BYTES;
        const uint32_t wbase = sb + 2 * TILE_BYTES + buf * TILE_BYTES;

        __syncthreads();   // previous stage's compute done -> buffers reusable

        if (tid < 128) {
            // zero own W row, then scatter this row's nnz (thread-private row)
            char* w = smem + 2 * TILE_BYTES + buf * TILE_BYTES + tid * 128;
            const unsigned swt = (tid & 7) << 4;
#pragma unroll
            for (int q = 0; q < 8; ++q)
                *reinterpret_cast<float4*>(w + ((q * 16) ^ swt)) =
                    make_float4(0.f, 0.f, 0.f, 0.f);
            int m  = m0 + tid;
            int lo = g_bound[s * M_DIM + m];
            int hi = g_bound[(s + 1) * M_DIM + m];
            for (int i = lo; i < hi; ++i) {
                uint32_t p = g_wpack[i];
                int c = (int)(p & 0xFFFFu) - s * KB;
                *reinterpret_cast<__half*>(w + ((c * 2) ^ swt)) =
                    __ushort_as_half((uint16_t)(p >> 16));
            }
        } else if (s + 1 < KSTAGES) {
            // issue next X tile into the other buffer
            const char* src0 = (const char*)(xrow0 + (size_t)(s + 1) * KB);
            const uint32_t xn = sb + ((s + 1) & 1) * TILE_BYTES;
            int t = tid - 128;
#pragma unroll
            for (int i = 0; i < 8; ++i) {
                int p = i * 128 + t;
                int n = p >> 3, q = p & 7;
                cp_async16(xn + n * 128 + ((q * 16) ^ ((n & 7) << 4)),
                           src0 + (size_t)n * (K_DIM * 2) + q * 16);
            }
        }
        cp_commit();       // uniform group count across all threads
        cp_wait1();        // X[s] landed (only X[s+1] may remain in flight)
        __syncthreads();   // X + W visible to all warps

        // ---- compute stage s: 4 k16-steps x (4 A-ldsm + 2 B-ldsm + 16 mma) ----
#pragma unroll
        for (int ks = 0; ks < 4; ++ks) {
            const int kb = ks * 32 + seg16;     // byte offset of this lane's k-half
            uint32_t a[4][4];
#pragma unroll
            for (int mt = 0; mt < 4; ++mt) {
                int row = arow + mt * 16;
                ldsm_x4(a[mt], wbase + row * 128 + (kb ^ ((row & 7) << 4)));
            }
#pragma unroll
            for (int np = 0; np < 2; ++np) {
                uint32_t bf[4];
                int row = brow + np * 16;
                ldsm_x4(bf, xbase + row * 128 + (kb ^ ((row & 7) << 4)));
                // bf: {n0-7|k0-7, n8-15|k0-7, n0-7|k8-15, n8-15|k8-15}
#pragma unroll
                for (int mt = 0; mt < 4; ++mt) {
                    mma16816(acc[mt][np * 2 + 0], a[mt], bf[0], bf[2]);
                    mma16816(acc[mt][np * 2 + 1], a[mt], bf[1], bf[3]);
                }
            }
        }
    }

    // ---- epilogue: out[b][m][n], float2 stores (n-contiguous pairs) ----
    {
        const int r = lane >> 2;
        const int c = (lane & 3) * 2;
        float* ob = out + ((size_t)b * M_DIM + m0 + wm) * N_DIM + n0 + wn;
#pragma unroll
        for (int mt = 0; mt < 4; ++mt) {
#pragma unroll
            for (int nt = 0; nt < 4; ++nt) {
                float* p0 = ob + (size_t)(mt * 16 + r) * N_DIM + nt * 8 + c;
                *reinterpret_cast<float2*>(p0) =
                    make_float2(acc[mt][nt][0], acc[mt][nt][1]);
                *reinterpret_cast<float2*>(p0 + 8 * N_DIM) =
                    make_float2(acc[mt][nt][2], acc[mt][nt][3]);
            }
        }
    }
}

// ---------------------------------------------------------------------------
// launch: inputs: x (f32), values (f32), row_offsets (i32), column_indices (i32)
// ---------------------------------------------------------------------------
extern "C" void kernel_launch(void* const* d_in, const int* in_sizes, int n_in,
                              void* d_out, int out_size) {
    const float* x    = (const float*)d_in[0];
    const float* vals = (const float*)d_in[1];
    const int*   cols = (const int*)d_in[3];
    float*       out  = (float*)d_out;
    (void)in_sizes; (void)n_in; (void)out_size;

    cudaFuncSetAttribute(spmm_hmma_kernel,
                         cudaFuncAttributeMaxDynamicSharedMemorySize, SM_TOTAL);

    // x -> fp16 (same layout)
    size_t n4 = (size_t)B_DIM * N_DIM * K_DIM / 4;
    convert_kernel<<<(unsigned)(n4 / 256), 256>>>(x);

    // CSR dedup + pack + stage bounds
    prep_kernel<<<(M_DIM + 255) / 256, 256>>>(vals, cols);

    // GEMM: grid (n-chunks x b, m-blocks)
    dim3 grid((N_DIM / TN) * B_DIM, M_DIM / TM);
    spmm_hmma_kernel<<<grid, 256, SM_TOTAL>>>(out);
}

// round 13
// speedup vs baseline: 3.3873x; 1.8646x over previous
#include <cuda_runtime.h>
#include <cuda_fp16.h>
#include <cstdint>

// ---------------- problem constants ----------------
#define M_DIM 4096
#define K_DIM 4096
#define B_DIM 4
#define N_DIM 2048
#define NNZR  409
#define NNZ_TOT (M_DIM * NNZR)

// ---------------- GEMM tiling ----------------
#define KB      64            // K per stage (64 fp16 = 128 B/row = one SW128 atom row)
#define KSTAGES (K_DIM / KB)  // 64
#define TM      128           // M rows per CTA (W side)
#define TN      128           // n columns per CTA (X side)
#define PSTAGES 3             // pipeline depth

// ---------------- static scratch (no runtime allocation) ----------------
__device__ __half g_xh[(size_t)B_DIM * N_DIM * K_DIM];   // x fp16, [B][N][K]
__device__ __half g_wh[(size_t)M_DIM * K_DIM];           // dense W fp16, [M][K]

// ---------------- SMEM: 3 stages x (X 16KB | W 16KB) ----------------
#define TILE_BYTES  16384
#define STAGE_BYTES (2 * TILE_BYTES)
#define SM_TOTAL    (PSTAGES * STAGE_BYTES)   // 98304 B

__device__ __forceinline__ uint32_t smem_u32(const void* p) {
    return (uint32_t)__cvta_generic_to_shared(p);
}
__device__ __forceinline__ void cp_async16(uint32_t dst, const void* src) {
    asm volatile("cp.async.cg.shared.global [%0], [%1], 16;" :: "r"(dst), "l"(src));
}
__device__ __forceinline__ void cp_commit() {
    asm volatile("cp.async.commit_group;");
}
__device__ __forceinline__ void cp_wait1() {
    asm volatile("cp.async.wait_group 1;" ::: "memory");
}
__device__ __forceinline__ void ldsm_x4(uint32_t* r, uint32_t addr) {
    asm volatile("ldmatrix.sync.aligned.m8n8.x4.shared.b16 {%0,%1,%2,%3}, [%4];"
                 : "=r"(r[0]), "=r"(r[1]), "=r"(r[2]), "=r"(r[3]) : "r"(addr));
}
__device__ __forceinline__ void mma16816(float* d, const uint32_t* a,
                                         uint32_t b0, uint32_t b1) {
    asm volatile(
        "mma.sync.aligned.m16n8k16.row.col.f32.f16.f16.f32 "
        "{%0,%1,%2,%3}, {%4,%5,%6,%7}, {%8,%9}, {%0,%1,%2,%3};"
        : "+f"(d[0]), "+f"(d[1]), "+f"(d[2]), "+f"(d[3])
        : "r"(a[0]), "r"(a[1]), "r"(a[2]), "r"(a[3]), "r"(b0), "r"(b1));
}

// ---------------------------------------------------------------------------
// Kernel 1: x fp32 -> fp16 (same [B][N][K] layout = mma B operand, K-major).
// ---------------------------------------------------------------------------
__global__ void convert_kernel(const float* __restrict__ x) {
    size_t i = ((size_t)blockIdx.x * blockDim.x + threadIdx.x) * 4;
    float4 v = *reinterpret_cast<const float4*>(x + i);
    __half2 h0 = __floats2half2_rn(v.x, v.y);
    __half2 h1 = __floats2half2_rn(v.z, v.w);
    uint2 pk = make_uint2(*(uint32_t*)&h0, *(uint32_t*)&h1);
    *reinterpret_cast<uint2*>(g_xh + i) = pk;
}

// ---------------------------------------------------------------------------
// Kernel 2a: zero the dense W (must happen every launch; graph replays).
// ---------------------------------------------------------------------------
__global__ void zero_w_kernel() {
    size_t i = (size_t)blockIdx.x * blockDim.x + threadIdx.x;
    reinterpret_cast<float4*>(g_wh)[i] = make_float4(0.f, 0.f, 0.f, 0.f);
}

// ---------------------------------------------------------------------------
// Kernel 2b: deterministic CSR -> dense scatter. Thread per row: columns are
// sorted, so duplicates are adjacent; merge them in fp32, store fp16 once.
// ---------------------------------------------------------------------------
__global__ void scatter_kernel(const float* __restrict__ vals,
                               const int*   __restrict__ cols) {
    int m = blockIdx.x * blockDim.x + threadIdx.x;
    if (m >= M_DIM) return;
    __half* wr = g_wh + (size_t)m * K_DIM;
    int rs = m * NNZR, re = rs + NNZR;
    int pc = -1;
    float sum = 0.f;
    for (int i = rs; i < re; ++i) {
        int   c = cols[i];
        float v = vals[i];
        if (c == pc) { sum += v; continue; }
        if (pc >= 0) wr[pc] = __float2half_rn(sum);
        pc = c; sum = v;
    }
    wr[pc] = __float2half_rn(sum);
}

// ---------------------------------------------------------------------------
// Kernel 3: dense fp16 HMMA GEMM, 3-stage cp.async pipeline, ONE barrier per
// stage. CTA = 128M x 128N; 8 warps (2m x 4n), warp tile 64x32.
// Swizzle: SW128 -> off ^ ((row&7)<<4).
// Schedule per stage s: wait_group(1) -> sync -> issue s+2 -> compute s.
// ---------------------------------------------------------------------------
extern __shared__ char smem[];

__device__ __forceinline__ void issue_stage(uint32_t sbuf, const char* xsrc,
                                            const char* wsrc, int tid) {
    // X: 1024 chunks of 16 B; W: 1024 chunks. 8 per thread.
#pragma unroll
    for (int i = 0; i < 4; ++i) {
        int p = i * 256 + tid;             // 0..1023 (X)
        int n = p >> 3, q = p & 7;
        cp_async16(sbuf + n * 128 + ((q * 16) ^ ((n & 7) << 4)),
                   xsrc + (size_t)n * (K_DIM * 2) + q * 16);
    }
#pragma unroll
    for (int i = 0; i < 4; ++i) {
        int p = i * 256 + tid;             // 0..1023 (W)
        int mr = p >> 3, q = p & 7;
        cp_async16(sbuf + TILE_BYTES + mr * 128 + ((q * 16) ^ ((mr & 7) << 4)),
                   wsrc + (size_t)mr * (K_DIM * 2) + q * 16);
    }
}

__global__ __launch_bounds__(256, 2)
void gemm_kernel(float* __restrict__ out) {
    const int tid  = threadIdx.x;
    const int lane = tid & 31;
    const int wid  = tid >> 5;

    const int mb  = blockIdx.x;            // 0..31  (fastest -> X tile shared)
    const int nch = blockIdx.y;            // 0..63
    const int b   = nch >> 4;
    const int n0  = (nch & 15) * TN;
    const int m0  = mb * TM;

    const uint32_t sb = smem_u32(smem);
    const char* xrow0 = (const char*)(g_xh + (size_t)(b * N_DIM + n0) * K_DIM);
    const char* wrow0 = (const char*)(g_wh + (size_t)m0 * K_DIM);

    // warp tile origin: 2 m-warps x 4 n-warps
    const int wm = (wid & 1) * 64;
    const int wn = (wid >> 1) * 32;
    const int arow = wm + (lane & 15);
    const int brow = wn + (lane & 15);
    const int seg16 = (lane >> 4) * 16;

    float acc[4][4][4];
#pragma unroll
    for (int mt = 0; mt < 4; ++mt)
#pragma unroll
        for (int nt = 0; nt < 4; ++nt)
#pragma unroll
            for (int r = 0; r < 4; ++r) acc[mt][nt][r] = 0.f;

    // ---- prologue: stages 0 and 1 ----
    issue_stage(sb, xrow0, wrow0, tid);
    cp_commit();
    issue_stage(sb + STAGE_BYTES, xrow0 + KB * 2, wrow0 + KB * 2, tid);
    cp_commit();

    for (int s = 0; s < KSTAGES; ++s) {
        const uint32_t xbase = sb + (s % PSTAGES) * STAGE_BYTES;
        const uint32_t wbase = xbase + TILE_BYTES;

        cp_wait1();        // stage s landed (s+1 may remain in flight)
        __syncthreads();   // visible to all; compute(s-1) finished by all

        // prefetch stage s+2 into the buffer stage s-1 just vacated
        if (s + 2 < KSTAGES) {
            issue_stage(sb + ((s + 2) % PSTAGES) * STAGE_BYTES,
                        xrow0 + (size_t)(s + 2) * (KB * 2),
                        wrow0 + (size_t)(s + 2) * (KB * 2), tid);
        }
        cp_commit();       // uniform group accounting (empty group ok)

        // ---- compute stage s: 4 k16-steps ----
#pragma unroll
        for (int ks = 0; ks < 4; ++ks) {
            const int kb = ks * 32 + seg16;
            uint32_t a[4][4];
#pragma unroll
            for (int mt = 0; mt < 4; ++mt) {
                int row = arow + mt * 16;
                ldsm_x4(a[mt], wbase + row * 128 + (kb ^ ((row & 7) << 4)));
            }
#pragma unroll
            for (int np = 0; np < 2; ++np) {
                uint32_t bf[4];
                int row = brow + np * 16;
                ldsm_x4(bf, xbase + row * 128 + (kb ^ ((row & 7) << 4)));
#pragma unroll
                for (int mt = 0; mt < 4; ++mt) {
                    mma16816(acc[mt][np * 2 + 0], a[mt], bf[0], bf[2]);
                    mma16816(acc[mt][np * 2 + 1], a[mt], bf[1], bf[3]);
                }
            }
        }
    }

    // ---- epilogue: out[b][m][n], float2 stores ----
    {
        const int r = lane >> 2;
        const int c = (lane & 3) * 2;
        float* ob = out + ((size_t)b * M_DIM + m0 + wm) * N_DIM + n0 + wn;
#pragma unroll
        for (int mt = 0; mt < 4; ++mt) {
#pragma unroll
            for (int nt = 0; nt < 4; ++nt) {
                float* p0 = ob + (size_t)(mt * 16 + r) * N_DIM + nt * 8 + c;
                *reinterpret_cast<float2*>(p0) =
                    make_float2(acc[mt][nt][0], acc[mt][nt][1]);
                *reinterpret_cast<float2*>(p0 + 8 * N_DIM) =
                    make_float2(acc[mt][nt][2], acc[mt][nt][3]);
            }
        }
    }
}

// ---------------------------------------------------------------------------
// launch: inputs: x (f32), values (f32), row_offsets (i32), column_indices (i32)
// ---------------------------------------------------------------------------
extern "C" void kernel_launch(void* const* d_in, const int* in_sizes, int n_in,
                              void* d_out, int out_size) {
    const float* x    = (const float*)d_in[0];
    const float* vals = (const float*)d_in[1];
    const int*   cols = (const int*)d_in[3];
    float*       out  = (float*)d_out;
    (void)in_sizes; (void)n_in; (void)out_size;

    cudaFuncSetAttribute(gemm_kernel,
                         cudaFuncAttributeMaxDynamicSharedMemorySize, SM_TOTAL);

    // x -> fp16
    size_t n4 = (size_t)B_DIM * N_DIM * K_DIM / 4;
    convert_kernel<<<(unsigned)(n4 / 256), 256>>>(x);

    // densify W: zero, then deterministic merge-scatter
    size_t w4 = (size_t)M_DIM * K_DIM / 8;   // float4 = 8 halfs
    zero_w_kernel<<<(unsigned)(w4 / 256), 256>>>();
    scatter_kernel<<<(M_DIM + 255) / 256, 256>>>(vals, cols);

    // dense GEMM: grid (m-blocks fastest, n-chunks x b)
    dim3 grid(M_DIM / TM, (N_DIM / TN) * B_DIM);
    gemm_kernel<<<grid, 256, SM_TOTAL>>>(out);
}

// round 15
// speedup vs baseline: 4.0252x; 1.1883x over previous
#include <cuda_runtime.h>
#include <cuda_fp16.h>
#include <cstdint>

// ---------------- problem constants ----------------
#define M_DIM 4096
#define K_DIM 4096
#define B_DIM 4
#define N_DIM 2048
#define NNZR  409
#define NNZ_TOT (M_DIM * NNZR)

// ---------------- GEMM tiling ----------------
#define KB      64            // K per stage (64 fp16 = 128 B = one SW128 atom row)
#define KSTAGES (K_DIM / KB)  // 64
#define TM      128           // M rows per CTA (W side)
#define TN      256           // n columns per CTA (X side)
#define PSTAGES 3             // pipeline depth

// ---------------- static scratch (no runtime allocation) ----------------
__device__ __half g_xh[(size_t)B_DIM * N_DIM * K_DIM];   // x fp16, [B][N][K]
__device__ __half g_wh[(size_t)M_DIM * K_DIM];           // dense W fp16, [M][K]

// ---------------- SMEM: 3 stages x (X 32KB | W 16KB) ----------------
#define XT_BYTES    32768                  // 256 rows x 128 B
#define WT_BYTES    16384                  // 128 rows x 128 B
#define STAGE_BYTES (XT_BYTES + WT_BYTES)  // 49152
#define SM_TOTAL    (PSTAGES * STAGE_BYTES)  // 147456 B -> 1 CTA/SM

__device__ __forceinline__ uint32_t smem_u32(const void* p) {
    return (uint32_t)__cvta_generic_to_shared(p);
}
__device__ __forceinline__ void cp_async16(uint32_t dst, const void* src) {
    asm volatile("cp.async.cg.shared.global [%0], [%1], 16;" :: "r"(dst), "l"(src));
}
__device__ __forceinline__ void cp_commit() {
    asm volatile("cp.async.commit_group;");
}
__device__ __forceinline__ void cp_wait1() {
    asm volatile("cp.async.wait_group 1;" ::: "memory");
}
__device__ __forceinline__ void ldsm_x4(uint32_t* r, uint32_t addr) {
    asm volatile("ldmatrix.sync.aligned.m8n8.x4.shared.b16 {%0,%1,%2,%3}, [%4];"
                 : "=r"(r[0]), "=r"(r[1]), "=r"(r[2]), "=r"(r[3]) : "r"(addr));
}
__device__ __forceinline__ void mma16816(float* d, const uint32_t* a,
                                         uint32_t b0, uint32_t b1) {
    asm volatile(
        "mma.sync.aligned.m16n8k16.row.col.f32.f16.f16.f32 "
        "{%0,%1,%2,%3}, {%4,%5,%6,%7}, {%8,%9}, {%0,%1,%2,%3};"
        : "+f"(d[0]), "+f"(d[1]), "+f"(d[2]), "+f"(d[3])
        : "r"(a[0]), "r"(a[1]), "r"(a[2]), "r"(a[3]), "r"(b0), "r"(b1));
}

// ---------------------------------------------------------------------------
// Kernel 1: x fp32 -> fp16 (same [B][N][K] layout = mma B operand, K-major).
// ---------------------------------------------------------------------------
__global__ void convert_kernel(const float* __restrict__ x) {
    size_t i = ((size_t)blockIdx.x * blockDim.x + threadIdx.x) * 4;
    float4 v = *reinterpret_cast<const float4*>(x + i);
    __half2 h0 = __floats2half2_rn(v.x, v.y);
    __half2 h1 = __floats2half2_rn(v.z, v.w);
    uint2 pk = make_uint2(*(uint32_t*)&h0, *(uint32_t*)&h1);
    *reinterpret_cast<uint2*>(g_xh + i) = pk;
}

// ---------------------------------------------------------------------------
// Kernel 2a: zero the dense W (every launch; graph replays).
// ---------------------------------------------------------------------------
__global__ void zero_w_kernel() {
    size_t i = (size_t)blockIdx.x * blockDim.x + threadIdx.x;
    reinterpret_cast<float4*>(g_wh)[i] = make_float4(0.f, 0.f, 0.f, 0.f);
}

// ---------------------------------------------------------------------------
// Kernel 2b: parallel deterministic CSR -> dense scatter, thread per NNZ.
// Columns sorted within a row => duplicates adjacent. The leader of each
// equal-run sums the run in fp32 and writes one fp16. No atomics.
// ---------------------------------------------------------------------------
__global__ void scatter_kernel(const float* __restrict__ vals,
                               const int*   __restrict__ cols) {
    int i = blockIdx.x * blockDim.x + threadIdx.x;
    if (i >= NNZ_TOT) return;
    int c  = cols[i];
    int m  = i / NNZR;
    int rs = m * NNZR;
    if (i > rs && cols[i - 1] == c) return;     // not a run leader
    float sum = vals[i];
    int re = rs + NNZR;
    for (int j = i + 1; j < re && cols[j] == c; ++j) sum += vals[j];
    g_wh[(size_t)m * K_DIM + c] = __float2half_rn(sum);
}

// ---------------------------------------------------------------------------
// Kernel 3: dense fp16 HMMA GEMM. CTA = 128M x 256N; 8 warps (2m x 4n),
// warp tile 64x64 => 0.25 ldsm.x4 per mma. 3-stage cp.async pipeline,
// one barrier per stage. Swizzle: SW128 -> off ^ ((row&7)<<4).
// Schedule per stage s: wait_group(1) -> sync -> issue s+2 -> compute s.
// ---------------------------------------------------------------------------
extern __shared__ char smem[];

__device__ __forceinline__ void issue_stage(uint32_t sbuf, const char* xsrc,
                                            const char* wsrc, int tid) {
    // X: 2048 chunks of 16 B (8/thread); W: 1024 chunks (4/thread).
#pragma unroll
    for (int i = 0; i < 8; ++i) {
        int p = i * 256 + tid;
        int n = p >> 3, q = p & 7;
        cp_async16(sbuf + n * 128 + ((q * 16) ^ ((n & 7) << 4)),
                   xsrc + (size_t)n * (K_DIM * 2) + q * 16);
    }
#pragma unroll
    for (int i = 0; i < 4; ++i) {
        int p = i * 256 + tid;
        int mr = p >> 3, q = p & 7;
        cp_async16(sbuf + XT_BYTES + mr * 128 + ((q * 16) ^ ((mr & 7) << 4)),
                   wsrc + (size_t)mr * (K_DIM * 2) + q * 16);
    }
}

__global__ __launch_bounds__(256, 1)
void gemm_kernel(float* __restrict__ out) {
    const int tid  = threadIdx.x;
    const int lane = tid & 31;
    const int wid  = tid >> 5;

    const int mb  = blockIdx.x;            // 0..31 (fastest -> X tile L2-shared)
    const int nch = blockIdx.y;            // 0..31
    const int b   = nch >> 3;
    const int n0  = (nch & 7) * TN;
    const int m0  = mb * TM;

    const uint32_t sb = smem_u32(smem);
    const char* xrow0 = (const char*)(g_xh + (size_t)(b * N_DIM + n0) * K_DIM);
    const char* wrow0 = (const char*)(g_wh + (size_t)m0 * K_DIM);

    // warp tile origin: 2 m-warps x 4 n-warps, each 64x64
    const int wm = (wid & 1) * 64;
    const int wn = (wid >> 1) * 64;
    const int arow = wm + (lane & 15);
    const int brow = wn + (lane & 15);
    const int seg16 = (lane >> 4) * 16;

    float acc[4][8][4];
#pragma unroll
    for (int mt = 0; mt < 4; ++mt)
#pragma unroll
        for (int nt = 0; nt < 8; ++nt)
#pragma unroll
            for (int r = 0; r < 4; ++r) acc[mt][nt][r] = 0.f;

    // ---- prologue: stages 0 and 1 ----
    issue_stage(sb, xrow0, wrow0, tid);
    cp_commit();
    issue_stage(sb + STAGE_BYTES, xrow0 + KB * 2, wrow0 + KB * 2, tid);
    cp_commit();

    for (int s = 0; s < KSTAGES; ++s) {
        const uint32_t xbase = sb + (s % PSTAGES) * STAGE_BYTES;
        const uint32_t wbase = xbase + XT_BYTES;

        cp_wait1();        // stage s landed (s+1 may remain in flight)
        __syncthreads();   // visible to all; compute(s-1) finished by all

        if (s + 2 < KSTAGES) {
            issue_stage(sb + ((s + 2) % PSTAGES) * STAGE_BYTES,
                        xrow0 + (size_t)(s + 2) * (KB * 2),
                        wrow0 + (size_t)(s + 2) * (KB * 2), tid);
        }
        cp_commit();       // uniform group accounting (empty group ok)

        // ---- compute stage s: 4 k16-steps, 8 ldsm + 32 mma each ----
#pragma unroll
        for (int ks = 0; ks < 4; ++ks) {
            const int kb = ks * 32 + seg16;
            uint32_t a[4][4];
#pragma unroll
            for (int mt = 0; mt < 4; ++mt) {
                int row = arow + mt * 16;
                ldsm_x4(a[mt], wbase + row * 128 + (kb ^ ((row & 7) << 4)));
            }
#pragma unroll
            for (int np = 0; np < 4; ++np) {
                uint32_t bf[4];
                int row = brow + np * 16;
                ldsm_x4(bf, xbase + row * 128 + (kb ^ ((row & 7) << 4)));
                // bf: {n0-7|k0-7, n8-15|k0-7, n0-7|k8-15, n8-15|k8-15}
#pragma unroll
                for (int mt = 0; mt < 4; ++mt) {
                    mma16816(acc[mt][np * 2 + 0], a[mt], bf[0], bf[2]);
                    mma16816(acc[mt][np * 2 + 1], a[mt], bf[1], bf[3]);
                }
            }
        }
    }

    // ---- epilogue: out[b][m][n], float2 stores ----
    {
        const int r = lane >> 2;
        const int c = (lane & 3) * 2;
        float* ob = out + ((size_t)b * M_DIM + m0 + wm) * N_DIM + n0 + wn;
#pragma unroll
        for (int mt = 0; mt < 4; ++mt) {
#pragma unroll
            for (int nt = 0; nt < 8; ++nt) {
                float* p0 = ob + (size_t)(mt * 16 + r) * N_DIM + nt * 8 + c;
                *reinterpret_cast<float2*>(p0) =
                    make_float2(acc[mt][nt][0], acc[mt][nt][1]);
                *reinterpret_cast<float2*>(p0 + 8 * N_DIM) =
                    make_float2(acc[mt][nt][2], acc[mt][nt][3]);
            }
        }
    }
}

// ---------------------------------------------------------------------------
// launch: inputs: x (f32), values (f32), row_offsets (i32), column_indices (i32)
// ---------------------------------------------------------------------------
extern "C" void kernel_launch(void* const* d_in, const int* in_sizes, int n_in,
                              void* d_out, int out_size) {
    const float* x    = (const float*)d_in[0];
    const float* vals = (const float*)d_in[1];
    const int*   cols = (const int*)d_in[3];
    float*       out  = (float*)d_out;
    (void)in_sizes; (void)n_in; (void)out_size;

    cudaFuncSetAttribute(gemm_kernel,
                         cudaFuncAttributeMaxDynamicSharedMemorySize, SM_TOTAL);

    // x -> fp16
    size_t n4 = (size_t)B_DIM * N_DIM * K_DIM / 4;
    convert_kernel<<<(unsigned)(n4 / 256), 256>>>(x);

    // densify W: zero, then parallel deterministic leader-scan scatter
    size_t w4 = (size_t)M_DIM * K_DIM / 8;   // float4 = 8 halfs
    zero_w_kernel<<<(unsigned)(w4 / 256), 256>>>();
    scatter_kernel<<<(NNZ_TOT + 255) / 256, 256>>>(vals, cols);

    // dense GEMM: grid (m-blocks fastest, n-chunks x b)
    dim3 grid(M_DIM / TM, (N_DIM / TN) * B_DIM);
    gemm_kernel<<<grid, 256, SM_TOTAL>>>(out);
}

// round 16
// speedup vs baseline: 4.0528x; 1.0069x over previous
#include <cuda_runtime.h>
#include <cuda_fp16.h>
#include <cstdint>

// ---------------- problem constants ----------------
#define M_DIM 4096
#define K_DIM 4096
#define B_DIM 4
#define N_DIM 2048
#define NNZR  409
#define NNZ_TOT (M_DIM * NNZR)

// ---------------- GEMM tiling ----------------
#define KB      64            // K per stage (64 fp16 = 128 B = one SW128 atom row)
#define KSTAGES (K_DIM / KB)  // 64
#define TM      128           // M rows per CTA (W side)
#define TN      256           // n columns per CTA (X side)
#define PSTAGES 4             // smem pipeline depth

// ---------------- static scratch (no runtime allocation) ----------------
__device__ __half g_xh[(size_t)B_DIM * N_DIM * K_DIM];   // x fp16, [B][N][K]
__device__ __half g_wh[(size_t)M_DIM * K_DIM];           // dense W fp16, [M][K]

// ---------------- SMEM: 4 stages x (X 32KB | W 16KB) ----------------
#define XT_BYTES    32768                  // 256 rows x 128 B
#define WT_BYTES    16384                  // 128 rows x 128 B
#define STAGE_BYTES (XT_BYTES + WT_BYTES)  // 49152
#define SM_TOTAL    (PSTAGES * STAGE_BYTES)  // 196608 B -> 1 CTA/SM

__device__ __forceinline__ uint32_t smem_u32(const void* p) {
    return (uint32_t)__cvta_generic_to_shared(p);
}
__device__ __forceinline__ void cp_async16(uint32_t dst, const void* src) {
    asm volatile("cp.async.cg.shared.global [%0], [%1], 16;" :: "r"(dst), "l"(src));
}
__device__ __forceinline__ void cp_commit() {
    asm volatile("cp.async.commit_group;");
}
__device__ __forceinline__ void cp_wait2() {
    asm volatile("cp.async.wait_group 2;" ::: "memory");
}
__device__ __forceinline__ void ldsm_x4(uint32_t* r, uint32_t addr) {
    asm volatile("ldmatrix.sync.aligned.m8n8.x4.shared.b16 {%0,%1,%2,%3}, [%4];"
                 : "=r"(r[0]), "=r"(r[1]), "=r"(r[2]), "=r"(r[3]) : "r"(addr));
}
__device__ __forceinline__ void mma16816(float* d, const uint32_t* a,
                                         uint32_t b0, uint32_t b1) {
    asm volatile(
        "mma.sync.aligned.m16n8k16.row.col.f32.f16.f16.f32 "
        "{%0,%1,%2,%3}, {%4,%5,%6,%7}, {%8,%9}, {%0,%1,%2,%3};"
        : "+f"(d[0]), "+f"(d[1]), "+f"(d[2]), "+f"(d[3])
        : "r"(a[0]), "r"(a[1]), "r"(a[2]), "r"(a[3]), "r"(b0), "r"(b1));
}

// ---------------------------------------------------------------------------
// Kernel 1: x fp32 -> fp16 (same [B][N][K] layout = mma B operand, K-major).
// ---------------------------------------------------------------------------
__global__ void convert_kernel(const float* __restrict__ x) {
    size_t i = ((size_t)blockIdx.x * blockDim.x + threadIdx.x) * 4;
    float4 v = *reinterpret_cast<const float4*>(x + i);
    __half2 h0 = __floats2half2_rn(v.x, v.y);
    __half2 h1 = __floats2half2_rn(v.z, v.w);
    uint2 pk = make_uint2(*(uint32_t*)&h0, *(uint32_t*)&h1);
    *reinterpret_cast<uint2*>(g_xh + i) = pk;
}

// ---------------------------------------------------------------------------
// Kernel 2a: zero the dense W (every launch; graph replays).
// ---------------------------------------------------------------------------
__global__ void zero_w_kernel() {
    size_t i = (size_t)blockIdx.x * blockDim.x + threadIdx.x;
    reinterpret_cast<float4*>(g_wh)[i] = make_float4(0.f, 0.f, 0.f, 0.f);
}

// ---------------------------------------------------------------------------
// Kernel 2b: parallel deterministic CSR -> dense scatter, thread per NNZ.
// Columns sorted within a row => duplicates adjacent. The leader of each
// equal-run sums the run in fp32 and writes one fp16. No atomics.
// ---------------------------------------------------------------------------
__global__ void scatter_kernel(const float* __restrict__ vals,
                               const int*   __restrict__ cols) {
    int i = blockIdx.x * blockDim.x + threadIdx.x;
    if (i >= NNZ_TOT) return;
    int c  = cols[i];
    int m  = i / NNZR;
    int rs = m * NNZR;
    if (i > rs && cols[i - 1] == c) return;     // not a run leader
    float sum = vals[i];
    int re = rs + NNZR;
    for (int j = i + 1; j < re && cols[j] == c; ++j) sum += vals[j];
    g_wh[(size_t)m * K_DIM + c] = __float2half_rn(sum);
}

// ---------------------------------------------------------------------------
// Kernel 3: dense fp16 HMMA GEMM. CTA = 128M x 256N; 8 warps (2m x 4n),
// warp tile 64x64 (0.25 ldsm.x4 per mma). 4-stage cp.async smem pipeline +
// explicit REGISTER double-buffering of fragments across k16-steps: while
// mma'ing k-step ks, the 8 ldsm for ks+1 are in flight -> no LDS-latency
// bubble at k-step boundaries. Swizzle: SW128 -> off ^ ((row&7)<<4).
// ---------------------------------------------------------------------------
extern __shared__ char smem[];

__device__ __forceinline__ void issue_stage(uint32_t sbuf, const char* xsrc,
                                            const char* wsrc, int tid) {
    // X: 2048 chunks of 16 B (8/thread); W: 1024 chunks (4/thread).
#pragma unroll
    for (int i = 0; i < 8; ++i) {
        int p = i * 256 + tid;
        int n = p >> 3, q = p & 7;
        cp_async16(sbuf + n * 128 + ((q * 16) ^ ((n & 7) << 4)),
                   xsrc + (size_t)n * (K_DIM * 2) + q * 16);
    }
#pragma unroll
    for (int i = 0; i < 4; ++i) {
        int p = i * 256 + tid;
        int mr = p >> 3, q = p & 7;
        cp_async16(sbuf + XT_BYTES + mr * 128 + ((q * 16) ^ ((mr & 7) << 4)),
                   wsrc + (size_t)mr * (K_DIM * 2) + q * 16);
    }
}

__global__ __launch_bounds__(256, 1)
void gemm_kernel(float* __restrict__ out) {
    const int tid  = threadIdx.x;
    const int lane = tid & 31;
    const int wid  = tid >> 5;

    const int mb  = blockIdx.x;            // 0..31 (fastest -> X tile L2-shared)
    const int nch = blockIdx.y;            // 0..31
    const int b   = nch >> 3;
    const int n0  = (nch & 7) * TN;
    const int m0  = mb * TM;

    const uint32_t sb = smem_u32(smem);
    const char* xrow0 = (const char*)(g_xh + (size_t)(b * N_DIM + n0) * K_DIM);
    const char* wrow0 = (const char*)(g_wh + (size_t)m0 * K_DIM);

    // warp tile origin: 2 m-warps x 4 n-warps, each 64x64
    const int wm = (wid & 1) * 64;
    const int wn = (wid >> 1) * 64;
    const int arow = wm + (lane & 15);
    const int brow = wn + (lane & 15);
    const int seg16 = (lane >> 4) * 16;

    float acc[4][8][4];
#pragma unroll
    for (int mt = 0; mt < 4; ++mt)
#pragma unroll
        for (int nt = 0; nt < 8; ++nt)
#pragma unroll
            for (int r = 0; r < 4; ++r) acc[mt][nt][r] = 0.f;

    // double-buffered operand fragments
    uint32_t afr[2][4][4];
    uint32_t bfr[2][4][4];

    // ---- prologue: stages 0,1,2 ----
    issue_stage(sb + 0 * STAGE_BYTES, xrow0,              wrow0,              tid);
    cp_commit();
    issue_stage(sb + 1 * STAGE_BYTES, xrow0 + KB * 2,     wrow0 + KB * 2,     tid);
    cp_commit();
    issue_stage(sb + 2 * STAGE_BYTES, xrow0 + 2 * KB * 2, wrow0 + 2 * KB * 2, tid);
    cp_commit();

    for (int s = 0; s < KSTAGES; ++s) {
        const uint32_t xbase = sb + (s & (PSTAGES - 1)) * STAGE_BYTES;
        const uint32_t wbase = xbase + XT_BYTES;

        cp_wait2();        // stage s landed (s+1, s+2 may remain in flight)
        __syncthreads();   // visible to all; compute(s-1) done by all

        // prefetch stage s+3 into the buffer stage s-1 just vacated
        if (s + 3 < KSTAGES) {
            issue_stage(sb + ((s + 3) & (PSTAGES - 1)) * STAGE_BYTES,
                        xrow0 + (size_t)(s + 3) * (KB * 2),
                        wrow0 + (size_t)(s + 3) * (KB * 2), tid);
        }
        cp_commit();       // uniform group accounting (empty group ok)

        // ---- load k-step 0 fragments into buffer 0 ----
        {
            const int kb = seg16;
#pragma unroll
            for (int mt = 0; mt < 4; ++mt) {
                int row = arow + mt * 16;
                ldsm_x4(afr[0][mt], wbase + row * 128 + (kb ^ ((row & 7) << 4)));
            }
#pragma unroll
            for (int np = 0; np < 4; ++np) {
                int row = brow + np * 16;
                ldsm_x4(bfr[0][np], xbase + row * 128 + (kb ^ ((row & 7) << 4)));
            }
        }

        // ---- 4 k16-steps, fragments double-buffered ----
#pragma unroll
        for (int ks = 0; ks < 4; ++ks) {
            const int cur = ks & 1;
            const int nxt = cur ^ 1;
            if (ks < 3) {   // issue next k-step's ldsm before consuming cur
                const int kb = (ks + 1) * 32 + seg16;
#pragma unroll
                for (int mt = 0; mt < 4; ++mt) {
                    int row = arow + mt * 16;
                    ldsm_x4(afr[nxt][mt], wbase + row * 128 + (kb ^ ((row & 7) << 4)));
                }
#pragma unroll
                for (int np = 0; np < 4; ++np) {
                    int row = brow + np * 16;
                    ldsm_x4(bfr[nxt][np], xbase + row * 128 + (kb ^ ((row & 7) << 4)));
                }
            }
#pragma unroll
            for (int np = 0; np < 4; ++np) {
#pragma unroll
                for (int mt = 0; mt < 4; ++mt) {
                    mma16816(acc[mt][np * 2 + 0], afr[cur][mt],
                             bfr[cur][np][0], bfr[cur][np][2]);
                    mma16816(acc[mt][np * 2 + 1], afr[cur][mt],
                             bfr[cur][np][1], bfr[cur][np][3]);
                }
            }
        }
    }

    // ---- epilogue: out[b][m][n], float2 stores ----
    {
        const int r = lane >> 2;
        const int c = (lane & 3) * 2;
        float* ob = out + ((size_t)b * M_DIM + m0 + wm) * N_DIM + n0 + wn;
#pragma unroll
        for (int mt = 0; mt < 4; ++mt) {
#pragma unroll
            for (int nt = 0; nt < 8; ++nt) {
                float* p0 = ob + (size_t)(mt * 16 + r) * N_DIM + nt * 8 + c;
                *reinterpret_cast<float2*>(p0) =
                    make_float2(acc[mt][nt][0], acc[mt][nt][1]);
                *reinterpret_cast<float2*>(p0 + 8 * N_DIM) =
                    make_float2(acc[mt][nt][2], acc[mt][nt][3]);
            }
        }
    }
}

// ---------------------------------------------------------------------------
// launch: inputs: x (f32), values (f32), row_offsets (i32), column_indices (i32)
// ---------------------------------------------------------------------------
extern "C" void kernel_launch(void* const* d_in, const int* in_sizes, int n_in,
                              void* d_out, int out_size) {
    const float* x    = (const float*)d_in[0];
    const float* vals = (const float*)d_in[1];
    const int*   cols = (const int*)d_in[3];
    float*       out  = (float*)d_out;
    (void)in_sizes; (void)n_in; (void)out_size;

    cudaFuncSetAttribute(gemm_kernel,
                         cudaFuncAttributeMaxDynamicSharedMemorySize, SM_TOTAL);

    // x -> fp16
    size_t n4 = (size_t)B_DIM * N_DIM * K_DIM / 4;
    convert_kernel<<<(unsigned)(n4 / 256), 256>>>(x);

    // densify W: zero, then parallel deterministic leader-scan scatter
    size_t w4 = (size_t)M_DIM * K_DIM / 8;   // float4 = 8 halfs
    zero_w_kernel<<<(unsigned)(w4 / 256), 256>>>();
    scatter_kernel<<<(NNZ_TOT + 255) / 256, 256>>>(vals, cols);

    // dense GEMM: grid (m-blocks fastest, n-chunks x b)
    dim3 grid(M_DIM / TM, (N_DIM / TN) * B_DIM);
    gemm_kernel<<<grid, 256, SM_TOTAL>>>(out);
}